// round 16
// baseline (speedup 1.0000x reference)
#include <cuda_runtime.h>
#include <cuda_bf16.h>
#include <cuda_fp16.h>
#include <cstdint>

#define NN 100000
#define NR 3
#define NE 300000

// ---- device scratch (no allocs allowed) ----
__device__ uint32_t g_z [(size_t)NN * 192];   // transformed feats, half2-packed
__device__ float    g_h1[(size_t)NN * 128];   // layer-1 output (pre-ReLU, f32)
__device__ float    g_outd[NR * NN];
__device__ float    g_ind [NR * NN];
__device__ int      g_cnt_in [NR * NN];
__device__ int      g_cnt_out[NR * NN];
__device__ int      g_off[NR * NN];
__device__ int      g_cur[NR * NN];
__device__ int      g_csr[NR * NE];
__device__ int      g_cursor;

// ------------------------------------------------------------------
__global__ void k_hist(const int* __restrict__ E) {
    int i = blockIdx.x * blockDim.x + threadIdx.x;
    if (i >= NR * NE) return;
    int r = i / NE, e = i % NE;
    const int* Er = E + (size_t)r * 2 * NE;
    atomicAdd(&g_cnt_out[r * NN + Er[e]],      1);
    atomicAdd(&g_cnt_in [r * NN + Er[NE + e]], 1);
}

__global__ void k_finalize_reserve() {
    int i = blockIdx.x * blockDim.x + threadIdx.x;
    int lane = threadIdx.x & 31;
    int d = 0;
    if (i < NR * NN) {
        int cin = g_cnt_in[i];
        g_outd[i] = rsqrtf(fmaxf((float)g_cnt_out[i], 1.f));
        g_ind [i] = rsqrtf(fmaxf((float)cin, 1.f));
        d = cin;
    }
    int s = d;
    #pragma unroll
    for (int o = 1; o < 32; o <<= 1) {
        int t = __shfl_up_sync(0xffffffffu, s, o);
        if (lane >= o) s += t;
    }
    int total = __shfl_sync(0xffffffffu, s, 31);
    int base = 0;
    if (lane == 31) base = atomicAdd(&g_cursor, total);
    base = __shfl_sync(0xffffffffu, base, 31);
    if (i < NR * NN) {
        int start = base + s - d;
        g_off[i] = start;
        g_cur[i] = start;
    }
}

__global__ void k_fill(const int* __restrict__ E) {
    int i = blockIdx.x * blockDim.x + threadIdx.x;
    if (i >= NR * NE) return;
    int r = i / NE, e = i % NE;
    const int* Er = E + (size_t)r * 2 * NE;
    int src = Er[e];
    int dst = Er[NE + e];
    int slot = atomicAdd(&g_cur[r * NN + dst], 1);
    g_csr[slot] = src;
}

// ------------------------------------------------------------------
__device__ __forceinline__ uint32_t pack_h2(float lo, float hi) {
    __half2 p = __floats2half2_rn(lo, hi);
    return *(uint32_t*)&p;
}

// split f into fp16 hi + fp16 lo residual
__device__ __forceinline__ void hsplit(float f, float& h, float& l) {
    __half hh = __float2half_rn(f);
    h = __half2float(hh);
    l = f - h;
}

__device__ __forceinline__ void mma_f16(float* c, const uint32_t* a, const uint32_t* b) {
    asm volatile(
        "mma.sync.aligned.m16n8k16.row.col.f32.f16.f16.f32 "
        "{%0,%1,%2,%3}, {%4,%5,%6,%7}, {%8,%9}, {%0,%1,%2,%3};"
        : "+f"(c[0]), "+f"(c[1]), "+f"(c[2]), "+f"(c[3])
        : "r"(a[0]), "r"(a[1]), "r"(a[2]), "r"(a[3]),
          "r"(b[0]), "r"(b[1]));
}

// Z[row][rel*BN + c] = outd_rel[row] * sum_k relu?(X[row][k]) * W[rel][k][c]
// fp16 2-pass split (X = hi+lo fp16, W = single fp16), m16n8k16.
// Block 128 x BN, 8 warps (4M x 2N). KC=128: whole K resident, single load
// phase, zero mid-k barriers. Output half2-packed uint32, stride WSTW words.
template<int BN, int WSTW>
__global__ __launch_bounds__(256) void k_gemm_tc(
    const float* __restrict__ X, const float* __restrict__ W,
    const float* __restrict__ outd, uint32_t* __restrict__ Z, int relu_in)
{
    constexpr int BM = 128;
    constexpr int K2 = 64;                // all 64 fp16x2 k-pairs
    constexpr int XST = BM + 8;           // 136: stride mod 32 == 8 -> conflict-free frag LDS
    constexpr int WST = BN + 8;
    constexpr int SXP = K2 * XST;         // one X plane (words)
    constexpr int WN = BN / 2;
    constexpr int NFR = WN / 8;

    extern __shared__ uint32_t smw[];
    uint32_t* xh = smw;                   // X hi plane [k2][row]
    uint32_t* xl = smw + SXP;             // X lo plane
    uint32_t* wf = smw + 2 * SXP;         // W fp16 plane [k2][n]

    int rel = blockIdx.y;
    const float* Wr = W + (size_t)rel * 128 * BN;
    const float* rs = outd + (size_t)rel * NN;
    int row0 = blockIdx.x * BM;
    int tid  = threadIdx.x;
    int warp = tid >> 5, lane = tid & 31;
    int wm = warp & 3, wn = warp >> 2;
    int m_w = wm * 32, n_w = wn * WN;

    float acc[2][NFR][4];
    #pragma unroll
    for (int i = 0; i < 2; i++)
        #pragma unroll
        for (int j = 0; j < NFR; j++)
            #pragma unroll
            for (int q = 0; q < 4; q++) acc[i][j][q] = 0.f;

    // ---- X tile [BM x 128] -> smem [k2][row], split fp16 hi/lo ----
    #pragma unroll
    for (int t = tid; t < BM * 32; t += 256) {
        int rr = t >> 5;                  // row
        int kq = t & 31;                  // float4 idx along k
        int row = row0 + rr;
        float4 v = make_float4(0.f, 0.f, 0.f, 0.f);
        if (row < NN) {
            v = *(const float4*)&X[(size_t)row * 128 + kq * 4];
            if (relu_in) {
                v.x = fmaxf(v.x, 0.f); v.y = fmaxf(v.y, 0.f);
                v.z = fmaxf(v.z, 0.f); v.w = fmaxf(v.w, 0.f);
            }
        }
        float hx, lx, hy, ly, hz, lz, hw, lw;
        hsplit(v.x, hx, lx); hsplit(v.y, hy, ly);
        hsplit(v.z, hz, lz); hsplit(v.w, hw, lw);
        xh[(kq * 2 + 0) * XST + rr] = pack_h2(hx, hy);
        xl[(kq * 2 + 0) * XST + rr] = pack_h2(lx, ly);
        xh[(kq * 2 + 1) * XST + rr] = pack_h2(hz, hw);
        xl[(kq * 2 + 1) * XST + rr] = pack_h2(lz, lw);
    }
    // ---- W tile [128 x BN] -> smem [k2][n], single fp16 ----
    #pragma unroll
    for (int t = tid; t < K2 * BN / 4; t += 256) {
        int k2 = t / (BN / 4);
        int nq = t % (BN / 4);
        float4 v0 = *(const float4*)&Wr[(size_t)(2 * k2)     * BN + nq * 4];
        float4 v1 = *(const float4*)&Wr[(size_t)(2 * k2 + 1) * BN + nq * 4];
        const float* p0 = &v0.x;
        const float* p1 = &v1.x;
        #pragma unroll
        for (int u = 0; u < 4; u++)
            wf[k2 * WST + nq * 4 + u] = pack_h2(p0[u], p1[u]);
    }
    __syncthreads();

    // ---- mainloop: 8 k16-steps, 2 passes each, no barriers ----
    #pragma unroll
    for (int ks = 0; ks < K2; ks += 8) {
        uint32_t ah[2][4], al[2][4];
        int ar = lane >> 2;
        int ac = ks + (lane & 3);
        #pragma unroll
        for (int i = 0; i < 2; i++) {
            int rb = m_w + i * 16 + ar;
            ah[i][0] = xh[ac * XST + rb];           al[i][0] = xl[ac * XST + rb];
            ah[i][1] = xh[ac * XST + rb + 8];       al[i][1] = xl[ac * XST + rb + 8];
            ah[i][2] = xh[(ac + 4) * XST + rb];     al[i][2] = xl[(ac + 4) * XST + rb];
            ah[i][3] = xh[(ac + 4) * XST + rb + 8]; al[i][3] = xl[(ac + 4) * XST + rb + 8];
        }
        #pragma unroll
        for (int j = 0; j < NFR; j++) {
            int nb = n_w + j * 8 + (lane >> 2);
            int kb = ks + (lane & 3);
            uint32_t b[2] = { wf[kb * WST + nb], wf[(kb + 4) * WST + nb] };
            #pragma unroll
            for (int i = 0; i < 2; i++) {
                mma_f16(acc[i][j], ah[i], b);
                mma_f16(acc[i][j], al[i], b);
            }
        }
    }

    // epilogue: scale by outd, pack to half2
    int cr = lane >> 2;
    int cc = (lane & 3) * 2;
    #pragma unroll
    for (int i = 0; i < 2; i++) {
        int r0g = row0 + m_w + i * 16 + cr;
        int r1g = r0g + 8;
        float s0 = (r0g < NN) ? rs[r0g] : 0.f;
        float s1 = (r1g < NN) ? rs[r1g] : 0.f;
        #pragma unroll
        for (int j = 0; j < NFR; j++) {
            int colw = (rel * BN + n_w + j * 8 + cc) >> 1;
            if (r0g < NN) {
                __half2 p = __floats2half2_rn(acc[i][j][0] * s0, acc[i][j][1] * s0);
                Z[(size_t)r0g * WSTW + colw] = *(uint32_t*)&p;
            }
            if (r1g < NN) {
                __half2 p = __floats2half2_rn(acc[i][j][2] * s1, acc[i][j][3] * s1);
                Z[(size_t)r1g * WSTW + colw] = *(uint32_t*)&p;
            }
        }
    }
}

// ------------------------------------------------------------------
__global__ __launch_bounds__(256) void k_gather128(
    const uint32_t* __restrict__ Z, const float* __restrict__ b1,
    float* __restrict__ O)
{
    int w = (blockIdx.x * blockDim.x + threadIdx.x) >> 5;
    int lane = threadIdx.x & 31;
    if (w >= NN) return;

    float4 tot = make_float4(0.f, 0.f, 0.f, 0.f);
    #pragma unroll
    for (int r = 0; r < NR; r++) {
        float4 b = *(const float4*)&b1[r * 128 + lane * 4];
        tot.x += b.x; tot.y += b.y; tot.z += b.z; tot.w += b.w;

        int idx = r * NN + w;
        int start = g_off[idx];
        int n = g_cnt_in[idx];
        float4 acc = make_float4(0.f, 0.f, 0.f, 0.f);
        int src = (n > 0) ? g_csr[start] : 0;
        for (int j = 0; j < n; j++) {
            int nsrc = (j + 1 < n) ? g_csr[start + j + 1] : 0;
            uint2 v = *(const uint2*)&Z[(size_t)src * 192 + r * 64 + lane * 2];
            float2 f0 = __half22float2(*(__half2*)&v.x);
            float2 f1 = __half22float2(*(__half2*)&v.y);
            acc.x += f0.x; acc.y += f0.y; acc.z += f1.x; acc.w += f1.y;
            src = nsrc;
        }
        float s = g_ind[idx];
        tot.x += s * acc.x; tot.y += s * acc.y; tot.z += s * acc.z; tot.w += s * acc.w;
    }
    *(float4*)&O[(size_t)w * 128 + lane * 4] = tot;
}

__global__ __launch_bounds__(256) void k_gather64(
    const uint32_t* __restrict__ Z, const float* __restrict__ b2,
    float* __restrict__ O)
{
    int w = (blockIdx.x * blockDim.x + threadIdx.x) >> 5;
    int lane = threadIdx.x & 31;
    if (w >= NN) return;

    float2 tot = make_float2(0.f, 0.f);
    #pragma unroll
    for (int r = 0; r < NR; r++) {
        float2 b = *(const float2*)&b2[r * 64 + lane * 2];
        tot.x += b.x; tot.y += b.y;

        int idx = r * NN + w;
        int start = g_off[idx];
        int n = g_cnt_in[idx];
        float2 acc = make_float2(0.f, 0.f);
        int src = (n > 0) ? g_csr[start] : 0;
        for (int j = 0; j < n; j++) {
            int nsrc = (j + 1 < n) ? g_csr[start + j + 1] : 0;
            uint32_t v = Z[(size_t)src * 96 + r * 32 + lane];
            float2 f = __half22float2(*(__half2*)&v);
            acc.x += f.x; acc.y += f.y;
            src = nsrc;
        }
        float s = g_ind[idx];
        tot.x += s * acc.x; tot.y += s * acc.y;
    }
    float2 o = make_float2(fmaxf(tot.x, 0.f), fmaxf(tot.y, 0.f));
    *(float2*)&O[(size_t)w * 64 + lane * 2] = o;
}

// ------------------------------------------------------------------
extern "C" void kernel_launch(void* const* d_in, const int* in_sizes, int n_in,
                              void* d_out, int out_size)
{
    const float* x  = (const float*)d_in[0];
    const float* W1 = (const float*)d_in[1];
    const float* b1 = (const float*)d_in[2];
    const float* W2 = (const float*)d_in[3];
    const float* b2 = (const float*)d_in[4];
    const int*   E  = (const int*)d_in[5];
    float* out = (float*)d_out;

    float *ph1, *poutd;
    uint32_t* pz;
    int *pcin, *pcout, *pcur_g;
    cudaGetSymbolAddress((void**)&pz,    g_z);
    cudaGetSymbolAddress((void**)&ph1,   g_h1);
    cudaGetSymbolAddress((void**)&poutd, g_outd);
    cudaGetSymbolAddress((void**)&pcin,  g_cnt_in);
    cudaGetSymbolAddress((void**)&pcout, g_cnt_out);
    cudaGetSymbolAddress((void**)&pcur_g, g_cursor);

    // dynamic smem: X 2 planes 64*136 + W plane 64*(BN+8), words -> bytes
    const int smem1 = (2 * 64 * 136 + 64 * (128 + 8)) * 4;  // 104448 B
    const int smem2 = (2 * 64 * 136 + 64 * (64 + 8))  * 4;  //  88064 B
    cudaFuncSetAttribute(k_gemm_tc<128, 192>, cudaFuncAttributeMaxDynamicSharedMemorySize, smem1);
    cudaFuncSetAttribute(k_gemm_tc<64, 96>,   cudaFuncAttributeMaxDynamicSharedMemorySize, smem2);

    // side stream + events, created once (first call runs outside capture)
    static cudaStream_t s2 = nullptr;
    static cudaEvent_t ev_fork = nullptr, ev_outd = nullptr, ev_join = nullptr;
    if (!s2) {
        cudaStreamCreateWithFlags(&s2, cudaStreamNonBlocking);
        cudaEventCreateWithFlags(&ev_fork, cudaEventDisableTiming);
        cudaEventCreateWithFlags(&ev_outd, cudaEventDisableTiming);
        cudaEventCreateWithFlags(&ev_join, cudaEventDisableTiming);
    }

    const int T = 256;

    // ---- fork CSR/degree chain onto s2 ----
    cudaEventRecord(ev_fork, 0);
    cudaStreamWaitEvent(s2, ev_fork, 0);

    cudaMemsetAsync(pcin,  0, NR * NN * sizeof(int), s2);
    cudaMemsetAsync(pcout, 0, NR * NN * sizeof(int), s2);
    cudaMemsetAsync(pcur_g, 0, sizeof(int), s2);
    k_hist            <<<(NR * NE + T - 1) / T, T, 0, s2>>>(E);
    k_finalize_reserve<<<(NR * NN + T - 1) / T, T, 0, s2>>>();
    cudaEventRecord(ev_outd, s2);            // outd/ind/off ready
    k_fill            <<<(NR * NE + T - 1) / T, T, 0, s2>>>(E);
    cudaEventRecord(ev_join, s2);            // full CSR ready

    // main stream: GEMM1 needs outd only; k_fill overlaps the GEMM
    cudaStreamWaitEvent(0, ev_outd, 0);
    k_gemm_tc<128, 192><<<dim3((NN + 127) / 128, NR), 256, smem1>>>(x, W1, poutd, pz, 0);

    // gather needs the filled CSR too
    cudaStreamWaitEvent(0, ev_join, 0);
    k_gather128<<<(NN * 32 + T - 1) / T, T>>>(pz, b1, ph1);

    // layer 2
    k_gemm_tc<64, 96><<<dim3((NN + 127) / 128, NR), 256, smem2>>>(ph1, W2, poutd, pz, 1);
    k_gather64<<<(NN * 32 + T - 1) / T, T>>>(pz, b2, out);
}

// round 17
// speedup vs baseline: 1.4372x; 1.4372x over previous
#include <cuda_runtime.h>
#include <cuda_bf16.h>
#include <cuda_fp16.h>
#include <cstdint>

#define NN 100000
#define NR 3
#define NE 300000

// ---- device scratch (no allocs allowed) ----
__device__ uint32_t g_z [(size_t)NN * 192];   // transformed feats, half2-packed
__device__ float    g_h1[(size_t)NN * 128];   // layer-1 output (pre-ReLU, f32)
__device__ float    g_outd[NR * NN];
__device__ float    g_ind [NR * NN];
__device__ int      g_cnt_in [NR * NN];
__device__ int      g_cnt_out[NR * NN];
__device__ int      g_off[NR * NN];
__device__ int      g_cur[NR * NN];
__device__ int      g_csr[NR * NE];
__device__ int      g_cursor;

// ------------------------------------------------------------------
__global__ void k_hist(const int* __restrict__ E) {
    int i = blockIdx.x * blockDim.x + threadIdx.x;
    if (i >= NR * NE) return;
    int r = i / NE, e = i % NE;
    const int* Er = E + (size_t)r * 2 * NE;
    atomicAdd(&g_cnt_out[r * NN + Er[e]],      1);
    atomicAdd(&g_cnt_in [r * NN + Er[NE + e]], 1);
}

__global__ void k_finalize_reserve() {
    int i = blockIdx.x * blockDim.x + threadIdx.x;
    int lane = threadIdx.x & 31;
    int d = 0;
    if (i < NR * NN) {
        int cin = g_cnt_in[i];
        g_outd[i] = rsqrtf(fmaxf((float)g_cnt_out[i], 1.f));
        g_ind [i] = rsqrtf(fmaxf((float)cin, 1.f));
        d = cin;
    }
    int s = d;
    #pragma unroll
    for (int o = 1; o < 32; o <<= 1) {
        int t = __shfl_up_sync(0xffffffffu, s, o);
        if (lane >= o) s += t;
    }
    int total = __shfl_sync(0xffffffffu, s, 31);
    int base = 0;
    if (lane == 31) base = atomicAdd(&g_cursor, total);
    base = __shfl_sync(0xffffffffu, base, 31);
    if (i < NR * NN) {
        int start = base + s - d;
        g_off[i] = start;
        g_cur[i] = start;
    }
}

__global__ void k_fill(const int* __restrict__ E) {
    int i = blockIdx.x * blockDim.x + threadIdx.x;
    if (i >= NR * NE) return;
    int r = i / NE, e = i % NE;
    const int* Er = E + (size_t)r * 2 * NE;
    int src = Er[e];
    int dst = Er[NE + e];
    int slot = atomicAdd(&g_cur[r * NN + dst], 1);
    g_csr[slot] = src;
}

// ------------------------------------------------------------------
__device__ __forceinline__ uint32_t pack_h2(float lo, float hi) {
    __half2 p = __floats2half2_rn(lo, hi);
    return *(uint32_t*)&p;
}

__device__ __forceinline__ void mma_f16(float* c, const uint32_t* a, const uint32_t* b) {
    asm volatile(
        "mma.sync.aligned.m16n8k16.row.col.f32.f16.f16.f32 "
        "{%0,%1,%2,%3}, {%4,%5,%6,%7}, {%8,%9}, {%0,%1,%2,%3};"
        : "+f"(c[0]), "+f"(c[1]), "+f"(c[2]), "+f"(c[3])
        : "r"(a[0]), "r"(a[1]), "r"(a[2]), "r"(a[3]),
          "r"(b[0]), "r"(b[1]));
}

// Z[row][rel*BN + c] = outd_rel[row] * sum_k relu?(X[row][k]) * W[rel][k][c]
// Single-pass fp16 x fp16 mma (m16n8k16). Block 128 x BN, 8 warps (4M x 2N).
// KC=64 (2 chunks), smem stride pad +8 => conflict-free mainloop LDS.
// Output half2-packed uint32, row stride WSTW words.
template<int BN, int WSTW>
__global__ __launch_bounds__(256) void k_gemm_tc(
    const float* __restrict__ X, const float* __restrict__ W,
    const float* __restrict__ outd, uint32_t* __restrict__ Z, int relu_in)
{
    constexpr int BM = 128, KC = 64;
    constexpr int K2 = KC / 2;            // 32 k2 per chunk
    constexpr int XST = BM + 8;           // 136: stride mod 32 == 8 -> conflict-free frag LDS
    constexpr int WST = BN + 8;
    constexpr int SXP = K2 * XST;
    constexpr int WN = BN / 2;
    constexpr int NFR = WN / 8;

    extern __shared__ uint32_t smw[];
    uint32_t* xf = smw;                   // X fp16 plane [k2][row]
    uint32_t* wf = smw + SXP;             // W fp16 plane [k2][n]

    int rel = blockIdx.y;
    const float* Wr = W + (size_t)rel * 128 * BN;
    const float* rs = outd + (size_t)rel * NN;
    int row0 = blockIdx.x * BM;
    int tid  = threadIdx.x;
    int warp = tid >> 5, lane = tid & 31;
    int wm = warp & 3, wn = warp >> 2;
    int m_w = wm * 32, n_w = wn * WN;

    float acc[2][NFR][4];
    #pragma unroll
    for (int i = 0; i < 2; i++)
        #pragma unroll
        for (int j = 0; j < NFR; j++)
            #pragma unroll
            for (int q = 0; q < 4; q++) acc[i][j][q] = 0.f;

    for (int k0 = 0; k0 < 128; k0 += KC) {
        // X tile [BM x KC] -> smem [k2][row], fp16 pack
        #pragma unroll
        for (int t = tid; t < BM * KC / 4; t += 256) {
            int rr = t / (KC / 4);
            int kq = t % (KC / 4);
            int row = row0 + rr;
            float4 v = make_float4(0.f, 0.f, 0.f, 0.f);
            if (row < NN) {
                v = *(const float4*)&X[(size_t)row * 128 + k0 + kq * 4];
                if (relu_in) {
                    v.x = fmaxf(v.x, 0.f); v.y = fmaxf(v.y, 0.f);
                    v.z = fmaxf(v.z, 0.f); v.w = fmaxf(v.w, 0.f);
                }
            }
            xf[(kq * 2 + 0) * XST + rr] = pack_h2(v.x, v.y);
            xf[(kq * 2 + 1) * XST + rr] = pack_h2(v.z, v.w);
        }
        // W tile [KC x BN] -> smem [k2][n], fp16 pack
        #pragma unroll
        for (int t = tid; t < K2 * BN / 4; t += 256) {
            int k2 = t / (BN / 4);
            int nq = t % (BN / 4);
            float4 v0 = *(const float4*)&Wr[(size_t)(k0 + 2 * k2)     * BN + nq * 4];
            float4 v1 = *(const float4*)&Wr[(size_t)(k0 + 2 * k2 + 1) * BN + nq * 4];
            const float* p0 = &v0.x;
            const float* p1 = &v1.x;
            #pragma unroll
            for (int u = 0; u < 4; u++)
                wf[k2 * WST + nq * 4 + u] = pack_h2(p0[u], p1[u]);
        }
        __syncthreads();

        #pragma unroll
        for (int ks = 0; ks < K2; ks += 8) {
            uint32_t af[2][4];
            int ar = lane >> 2;
            int ac = ks + (lane & 3);
            #pragma unroll
            for (int i = 0; i < 2; i++) {
                int rb = m_w + i * 16 + ar;
                af[i][0] = xf[ac * XST + rb];
                af[i][1] = xf[ac * XST + rb + 8];
                af[i][2] = xf[(ac + 4) * XST + rb];
                af[i][3] = xf[(ac + 4) * XST + rb + 8];
            }
            #pragma unroll
            for (int j = 0; j < NFR; j++) {
                int nb = n_w + j * 8 + (lane >> 2);
                int kb = ks + (lane & 3);
                uint32_t b[2] = { wf[kb * WST + nb], wf[(kb + 4) * WST + nb] };
                #pragma unroll
                for (int i = 0; i < 2; i++)
                    mma_f16(acc[i][j], af[i], b);
            }
        }
        __syncthreads();
    }

    // epilogue: scale by outd, pack to half2
    int cr = lane >> 2;
    int cc = (lane & 3) * 2;
    #pragma unroll
    for (int i = 0; i < 2; i++) {
        int r0g = row0 + m_w + i * 16 + cr;
        int r1g = r0g + 8;
        float s0 = (r0g < NN) ? rs[r0g] : 0.f;
        float s1 = (r1g < NN) ? rs[r1g] : 0.f;
        #pragma unroll
        for (int j = 0; j < NFR; j++) {
            int colw = (rel * BN + n_w + j * 8 + cc) >> 1;
            if (r0g < NN) {
                __half2 p = __floats2half2_rn(acc[i][j][0] * s0, acc[i][j][1] * s0);
                Z[(size_t)r0g * WSTW + colw] = *(uint32_t*)&p;
            }
            if (r1g < NN) {
                __half2 p = __floats2half2_rn(acc[i][j][2] * s1, acc[i][j][3] * s1);
                Z[(size_t)r1g * WSTW + colw] = *(uint32_t*)&p;
            }
        }
    }
}

// ------------------------------------------------------------------
__global__ __launch_bounds__(256) void k_gather128(
    const uint32_t* __restrict__ Z, const float* __restrict__ b1,
    float* __restrict__ O)
{
    int w = (blockIdx.x * blockDim.x + threadIdx.x) >> 5;
    int lane = threadIdx.x & 31;
    if (w >= NN) return;

    float4 tot = make_float4(0.f, 0.f, 0.f, 0.f);
    #pragma unroll
    for (int r = 0; r < NR; r++) {
        float4 b = *(const float4*)&b1[r * 128 + lane * 4];
        tot.x += b.x; tot.y += b.y; tot.z += b.z; tot.w += b.w;

        int idx = r * NN + w;
        int start = g_off[idx];
        int n = g_cnt_in[idx];
        float4 acc = make_float4(0.f, 0.f, 0.f, 0.f);
        int src = (n > 0) ? g_csr[start] : 0;
        for (int j = 0; j < n; j++) {
            int nsrc = (j + 1 < n) ? g_csr[start + j + 1] : 0;
            uint2 v = *(const uint2*)&Z[(size_t)src * 192 + r * 64 + lane * 2];
            float2 f0 = __half22float2(*(__half2*)&v.x);
            float2 f1 = __half22float2(*(__half2*)&v.y);
            acc.x += f0.x; acc.y += f0.y; acc.z += f1.x; acc.w += f1.y;
            src = nsrc;
        }
        float s = g_ind[idx];
        tot.x += s * acc.x; tot.y += s * acc.y; tot.z += s * acc.z; tot.w += s * acc.w;
    }
    *(float4*)&O[(size_t)w * 128 + lane * 4] = tot;
}

__global__ __launch_bounds__(256) void k_gather64(
    const uint32_t* __restrict__ Z, const float* __restrict__ b2,
    float* __restrict__ O)
{
    int w = (blockIdx.x * blockDim.x + threadIdx.x) >> 5;
    int lane = threadIdx.x & 31;
    if (w >= NN) return;

    float2 tot = make_float2(0.f, 0.f);
    #pragma unroll
    for (int r = 0; r < NR; r++) {
        float2 b = *(const float2*)&b2[r * 64 + lane * 2];
        tot.x += b.x; tot.y += b.y;

        int idx = r * NN + w;
        int start = g_off[idx];
        int n = g_cnt_in[idx];
        float2 acc = make_float2(0.f, 0.f);
        int src = (n > 0) ? g_csr[start] : 0;
        for (int j = 0; j < n; j++) {
            int nsrc = (j + 1 < n) ? g_csr[start + j + 1] : 0;
            uint32_t v = Z[(size_t)src * 96 + r * 32 + lane];
            float2 f = __half22float2(*(__half2*)&v);
            acc.x += f.x; acc.y += f.y;
            src = nsrc;
        }
        float s = g_ind[idx];
        tot.x += s * acc.x; tot.y += s * acc.y;
    }
    float2 o = make_float2(fmaxf(tot.x, 0.f), fmaxf(tot.y, 0.f));
    *(float2*)&O[(size_t)w * 64 + lane * 2] = o;
}

// ------------------------------------------------------------------
extern "C" void kernel_launch(void* const* d_in, const int* in_sizes, int n_in,
                              void* d_out, int out_size)
{
    const float* x  = (const float*)d_in[0];
    const float* W1 = (const float*)d_in[1];
    const float* b1 = (const float*)d_in[2];
    const float* W2 = (const float*)d_in[3];
    const float* b2 = (const float*)d_in[4];
    const int*   E  = (const int*)d_in[5];
    float* out = (float*)d_out;

    float *ph1, *poutd;
    uint32_t* pz;
    int *pcin, *pcout, *pcur_g;
    cudaGetSymbolAddress((void**)&pz,    g_z);
    cudaGetSymbolAddress((void**)&ph1,   g_h1);
    cudaGetSymbolAddress((void**)&poutd, g_outd);
    cudaGetSymbolAddress((void**)&pcin,  g_cnt_in);
    cudaGetSymbolAddress((void**)&pcout, g_cnt_out);
    cudaGetSymbolAddress((void**)&pcur_g, g_cursor);

    // dynamic smem: X plane 32*136 + W plane 32*(BN+8), words -> bytes
    const int smem1 = (32 * 136 + 32 * (128 + 8)) * 4;  // 34816 B
    const int smem2 = (32 * 136 + 32 * (64 + 8))  * 4;  // 26624 B
    cudaFuncSetAttribute(k_gemm_tc<128, 192>, cudaFuncAttributeMaxDynamicSharedMemorySize, smem1);
    cudaFuncSetAttribute(k_gemm_tc<64, 96>,   cudaFuncAttributeMaxDynamicSharedMemorySize, smem2);

    // side stream + events, created once (first call runs outside capture)
    static cudaStream_t s2 = nullptr;
    static cudaEvent_t ev_fork = nullptr, ev_outd = nullptr, ev_join = nullptr;
    if (!s2) {
        cudaStreamCreateWithFlags(&s2, cudaStreamNonBlocking);
        cudaEventCreateWithFlags(&ev_fork, cudaEventDisableTiming);
        cudaEventCreateWithFlags(&ev_outd, cudaEventDisableTiming);
        cudaEventCreateWithFlags(&ev_join, cudaEventDisableTiming);
    }

    const int T = 256;

    // ---- fork CSR/degree chain onto s2 ----
    cudaEventRecord(ev_fork, 0);
    cudaStreamWaitEvent(s2, ev_fork, 0);

    cudaMemsetAsync(pcin,  0, NR * NN * sizeof(int), s2);
    cudaMemsetAsync(pcout, 0, NR * NN * sizeof(int), s2);
    cudaMemsetAsync(pcur_g, 0, sizeof(int), s2);
    k_hist            <<<(NR * NE + T - 1) / T, T, 0, s2>>>(E);
    k_finalize_reserve<<<(NR * NN + T - 1) / T, T, 0, s2>>>();
    cudaEventRecord(ev_outd, s2);            // outd/ind/off ready
    k_fill            <<<(NR * NE + T - 1) / T, T, 0, s2>>>(E);
    cudaEventRecord(ev_join, s2);            // full CSR ready

    // main stream: GEMM1 needs outd only; k_fill overlaps the GEMM
    cudaStreamWaitEvent(0, ev_outd, 0);
    k_gemm_tc<128, 192><<<dim3((NN + 127) / 128, NR), 256, smem1>>>(x, W1, poutd, pz, 0);

    // gather needs the filled CSR too
    cudaStreamWaitEvent(0, ev_join, 0);
    k_gather128<<<(NN * 32 + T - 1) / T, T>>>(pz, b1, ph1);

    // layer 2
    k_gemm_tc<64, 96><<<dim3((NN + 127) / 128, NR), 256, smem2>>>(ph1, W2, poutd, pz, 1);
    k_gather64<<<(NN * 32 + T - 1) / T, T>>>(pz, b2, out);
}